// round 7
// baseline (speedup 1.0000x reference)
#include <cuda_runtime.h>
#include <cuda_fp16.h>

// Problem constants: N=100000, E=1600000, DIM=128, HEADS=8, HEAD_DIM=16
#define NMAX 100000
#define EMAX 1600000

static __device__ __half g_xh_h[NMAX * 128];   // projected features, fp16 [N,128]
static __device__ float  g_asrc[NMAX * 8];     // per-node src logits [N,H]
static __device__ float  g_adst[NMAX * 8];     // per-node dst logits [N,H]
static __device__ int    g_cnt[NMAX];          // in-degree
static __device__ int    g_off[NMAX];          // CSR offsets
static __device__ int    g_bsum[128];          // scan block sums
static __device__ int    g_epos[EMAX];         // within-segment position per edge
static __device__ int    g_csrc[EMAX];         // CSR: src per dst-sorted edge

// ---------------------------------------------------------------------------
__device__ __forceinline__ void ffma2(unsigned long long& d, unsigned long long a,
                                      unsigned long long b, unsigned long long c) {
    asm("fma.rn.f32x2 %0, %1, %2, %3;" : "=l"(d) : "l"(a), "l"(b), "l"(c));
}
__device__ __forceinline__ unsigned long long dup2(float v) {
    unsigned long long r;
    asm("mov.b64 %0, {%1, %1};" : "=l"(r) : "f"(v));
    return r;
}
__device__ __forceinline__ float2 unpk2(unsigned long long v) {
    float2 f;
    asm("mov.b64 {%0, %1}, %2;" : "=f"(f.x), "=f"(f.y) : "l"(v));
    return f;
}
__device__ __forceinline__ float lrelu(float s) { return (s > 0.f) ? s : 0.2f * s; }

// ---------------------------------------------------------------------------
// Kernel 1: xh = x @ W^T + b_proj (f32x2 packed FMA); epilogue stores fp16 xh
// and fused per-(row,head) attention logits.
// ---------------------------------------------------------------------------
__global__ __launch_bounds__(256) void gemm_kernel(const float* __restrict__ x,
                                                   const float* __restrict__ W,
                                                   const float* __restrict__ b,
                                                   const float* __restrict__ att_s,
                                                   const float* __restrict__ att_d,
                                                   int n) {
    __shared__ float xs[32 * 66];    // [k][row]
    __shared__ float wt[32 * 132];   // [k][c]

    const int t  = threadIdx.x;
    const int tx = t & 31;
    const int ty = t >> 5;
    const int row0 = blockIdx.x * 64;

    unsigned long long acc[4][4];
#pragma unroll
    for (int p = 0; p < 4; p++)
#pragma unroll
        for (int j = 0; j < 4; j++) acc[p][j] = 0ULL;

    for (int kt = 0; kt < 4; kt++) {
        const int k0 = kt * 32;
#pragma unroll
        for (int i = 0; i < 8; i++) {
            int idx = t + i * 256;
            int r = idx >> 5, k = idx & 31;
            int row = row0 + r;
            xs[k * 66 + r] = (row < n) ? x[row * 128 + k0 + k] : 0.f;
        }
#pragma unroll
        for (int i = 0; i < 16; i++) {
            int idx = t + i * 256;
            int c = idx >> 5, k = idx & 31;
            wt[k * 132 + c] = W[c * 128 + k0 + k];
        }
        __syncthreads();
#pragma unroll
        for (int k = 0; k < 32; k++) {
            float4 w4 = *reinterpret_cast<const float4*>(&wt[k * 132 + tx * 4]);
            unsigned long long wd0 = dup2(w4.x), wd1 = dup2(w4.y);
            unsigned long long wd2 = dup2(w4.z), wd3 = dup2(w4.w);
#pragma unroll
            for (int p = 0; p < 4; p++) {
                unsigned long long xp =
                    *reinterpret_cast<const unsigned long long*>(&xs[k * 66 + ty * 8 + p * 2]);
                ffma2(acc[p][0], xp, wd0, acc[p][0]);
                ffma2(acc[p][1], xp, wd1, acc[p][1]);
                ffma2(acc[p][2], xp, wd2, acc[p][2]);
                ffma2(acc[p][3], xp, wd3, acc[p][3]);
            }
        }
        __syncthreads();
    }

    float4 bb  = *reinterpret_cast<const float4*>(&b[tx * 4]);
    float4 as4 = *reinterpret_cast<const float4*>(&att_s[tx * 4]);
    float4 ad4 = *reinterpret_cast<const float4*>(&att_d[tx * 4]);
    const int h = tx >> 2;

#pragma unroll
    for (int p = 0; p < 4; p++) {
        float2 a0 = unpk2(acc[p][0]), a1 = unpk2(acc[p][1]);
        float2 a2 = unpk2(acc[p][2]), a3 = unpk2(acc[p][3]);
#pragma unroll
        for (int half = 0; half < 2; half++) {
            int row = row0 + ty * 8 + p * 2 + half;
            float4 o;
            if (half == 0) o = make_float4(a0.x + bb.x, a1.x + bb.y, a2.x + bb.z, a3.x + bb.w);
            else           o = make_float4(a0.y + bb.x, a1.y + bb.y, a2.y + bb.z, a3.y + bb.w);
            bool valid = (row < n);
            if (valid) {
                union { __half2 h2[2]; uint2 u; } pk;
                pk.h2[0] = __floats2half2_rn(o.x, o.y);
                pk.h2[1] = __floats2half2_rn(o.z, o.w);
                *reinterpret_cast<uint2*>(&g_xh_h[row * 128 + tx * 4]) = pk.u;
            }
            float ps = o.x * as4.x + o.y * as4.y + o.z * as4.z + o.w * as4.w;
            float pd = o.x * ad4.x + o.y * ad4.y + o.z * ad4.z + o.w * ad4.w;
            ps += __shfl_xor_sync(0xffffffffu, ps, 1);
            ps += __shfl_xor_sync(0xffffffffu, ps, 2);
            pd += __shfl_xor_sync(0xffffffffu, pd, 1);
            pd += __shfl_xor_sync(0xffffffffu, pd, 2);
            if (valid && (tx & 3) == 0) {
                g_asrc[row * 8 + h] = ps;
                g_adst[row * 8 + h] = pd;
            }
        }
    }
}

// ---------------------------------------------------------------------------
// CSR construction
// ---------------------------------------------------------------------------
__global__ __launch_bounds__(256) void zero_kernel(int n) {
    int t = blockIdx.x * 256 + threadIdx.x;
    if (t < n) g_cnt[t] = 0;
}

__global__ __launch_bounds__(256) void hist_kernel(const int* __restrict__ ei, int E) {
    int e = blockIdx.x * 256 + threadIdx.x;
    if (e < E) g_epos[e] = atomicAdd(&g_cnt[ei[E + e]], 1);
}

__global__ __launch_bounds__(256) void scan1_kernel(int n) {
    __shared__ int s[256];
    int b = blockIdx.x, t = threadIdx.x;
    int base = b * 1024 + t * 4;
    int v[4];
#pragma unroll
    for (int j = 0; j < 4; j++) v[j] = (base + j < n) ? g_cnt[base + j] : 0;
    int local = v[0] + v[1] + v[2] + v[3];
    s[t] = local;
    __syncthreads();
    for (int off = 1; off < 256; off <<= 1) {
        int xv = (t >= off) ? s[t - off] : 0;
        __syncthreads();
        s[t] += xv;
        __syncthreads();
    }
    int run = s[t] - local;
#pragma unroll
    for (int j = 0; j < 4; j++) {
        if (base + j < n) g_off[base + j] = run;
        run += v[j];
    }
    if (t == 255) g_bsum[b] = s[255];
}

__global__ __launch_bounds__(256) void scan3_kernel(int n, int nb) {
    __shared__ int s[128];
    int b = blockIdx.x, t = threadIdx.x;
    if (t < 128) s[t] = (t < b) ? g_bsum[t] : 0;
    __syncthreads();
    if (t < 64) s[t] += s[t + 64];
    __syncthreads();
    if (t < 32) {
        int v = s[t] + s[t + 32];
        v += __shfl_down_sync(0xffffffffu, v, 16);
        v += __shfl_down_sync(0xffffffffu, v, 8);
        v += __shfl_down_sync(0xffffffffu, v, 4);
        v += __shfl_down_sync(0xffffffffu, v, 2);
        v += __shfl_down_sync(0xffffffffu, v, 1);
        if (t == 0) s[0] = v;
    }
    __syncthreads();
    int add = s[0];
    int base = b * 1024 + t * 4;
#pragma unroll
    for (int j = 0; j < 4; j++)
        if (base + j < n) g_off[base + j] += add;
}

__global__ __launch_bounds__(256) void fill_kernel(const int* __restrict__ ei, int E) {
    int e = blockIdx.x * 256 + threadIdx.x;
    if (e >= E) return;
    g_csrc[g_off[ei[E + e]] + g_epos[e]] = ei[e];
}

// ---------------------------------------------------------------------------
// Fused gather v3: 2 warps/CTA, one node per warp.
// Prefetch phase per 32-edge chunk: lane l loads edge l's csrc + full 8-head
// src-logit row (2x LDG.128), computes all 8 exps, stores them to SMEM
// (pitch 9 -> conflict-free STS.32 and broadcast LDS).
// Accumulate phase: per edge, 1 broadcast LDS for the weight + 1 xh uint2 load.
// Kills the 8-wavefront-per-edge scattered logit LDGs.
// ---------------------------------------------------------------------------
__global__ __launch_bounds__(64) void gather_kernel(const float* __restrict__ bias,
                                                    float* __restrict__ out, int n) {
    __shared__ float s_ex[2][32 * 9];
    const int wid  = threadIdx.x >> 5;
    const int lane = threadIdx.x & 31;
    const int node = blockIdx.x * 2 + wid;
    if (node >= n) return;
    const uint2* xh2 = reinterpret_cast<const uint2*>(g_xh_h);
    const int hoff = lane >> 2;
    float* sex = s_ex[wid];

    // full per-head dst logits (same address across warp -> broadcast loads)
    const float4 ad0 = __ldg(reinterpret_cast<const float4*>(g_adst + node * 8));
    const float4 ad1 = __ldg(reinterpret_cast<const float4*>(g_adst + node * 8 + 4));

    // self loop (scalar broadcast loads for this lane's head)
    float s0 = __ldg(&g_asrc[node * 8 + hoff]) + __ldg(&g_adst[node * 8 + hoff]);
    float ex = __expf(lrelu(s0));
    float dsum = ex;

    uint2 sv = __ldg(&xh2[node * 32 + lane]);
    float2 f0 = __half22float2(*reinterpret_cast<__half2*>(&sv.x));
    float2 f1 = __half22float2(*reinterpret_cast<__half2*>(&sv.y));
    float4 acc = {ex * f0.x, ex * f0.y, ex * f1.x, ex * f1.y};

    const int beg = __ldg(&g_off[node]), cnt = __ldg(&g_cnt[node]);

    for (int c0 = 0; c0 < cnt; c0 += 32) {
        const int rem = min(cnt - c0, 32);
        int myidx = 0;
        if (lane < rem) {
            myidx = __ldg(&g_csrc[beg + c0 + lane]);
            float4 sa0 = __ldg(reinterpret_cast<const float4*>(g_asrc + myidx * 8));
            float4 sa1 = __ldg(reinterpret_cast<const float4*>(g_asrc + myidx * 8 + 4));
            float* sl = &sex[lane * 9];
            sl[0] = __expf(lrelu(sa0.x + ad0.x));
            sl[1] = __expf(lrelu(sa0.y + ad0.y));
            sl[2] = __expf(lrelu(sa0.z + ad0.z));
            sl[3] = __expf(lrelu(sa0.w + ad0.w));
            sl[4] = __expf(lrelu(sa1.x + ad1.x));
            sl[5] = __expf(lrelu(sa1.y + ad1.y));
            sl[6] = __expf(lrelu(sa1.z + ad1.z));
            sl[7] = __expf(lrelu(sa1.w + ad1.w));
        }
        __syncwarp();

        int j = 0;
        for (; j + 4 <= rem; j += 4) {
            int sA = __shfl_sync(0xffffffffu, myidx, j);
            int sB = __shfl_sync(0xffffffffu, myidx, j + 1);
            int sC = __shfl_sync(0xffffffffu, myidx, j + 2);
            int sD = __shfl_sync(0xffffffffu, myidx, j + 3);
            float eA = sex[(j    ) * 9 + hoff];
            float eB = sex[(j + 1) * 9 + hoff];
            float eC = sex[(j + 2) * 9 + hoff];
            float eD = sex[(j + 3) * 9 + hoff];
            uint2 vA = __ldg(&xh2[sA * 32 + lane]);
            uint2 vB = __ldg(&xh2[sB * 32 + lane]);
            uint2 vC = __ldg(&xh2[sC * 32 + lane]);
            uint2 vD = __ldg(&xh2[sD * 32 + lane]);
            dsum += eA + eB + eC + eD;
            float2 a0 = __half22float2(*reinterpret_cast<__half2*>(&vA.x));
            float2 a1 = __half22float2(*reinterpret_cast<__half2*>(&vA.y));
            float2 b0 = __half22float2(*reinterpret_cast<__half2*>(&vB.x));
            float2 b1 = __half22float2(*reinterpret_cast<__half2*>(&vB.y));
            float2 c0v = __half22float2(*reinterpret_cast<__half2*>(&vC.x));
            float2 c1 = __half22float2(*reinterpret_cast<__half2*>(&vC.y));
            float2 d0 = __half22float2(*reinterpret_cast<__half2*>(&vD.x));
            float2 d1 = __half22float2(*reinterpret_cast<__half2*>(&vD.y));
            acc.x += eA * a0.x + eB * b0.x + eC * c0v.x + eD * d0.x;
            acc.y += eA * a0.y + eB * b0.y + eC * c0v.y + eD * d0.y;
            acc.z += eA * a1.x + eB * b1.x + eC * c1.x + eD * d1.x;
            acc.w += eA * a1.y + eB * b1.y + eC * c1.y + eD * d1.y;
        }
        for (; j < rem; j++) {
            int s = __shfl_sync(0xffffffffu, myidx, j);
            float e = sex[j * 9 + hoff];
            dsum += e;
            uint2 v = __ldg(&xh2[s * 32 + lane]);
            float2 p0 = __half22float2(*reinterpret_cast<__half2*>(&v.x));
            float2 p1 = __half22float2(*reinterpret_cast<__half2*>(&v.y));
            acc.x += e * p0.x; acc.y += e * p0.y; acc.z += e * p1.x; acc.w += e * p1.y;
        }
        __syncwarp();
    }

    float inv = 1.0f / dsum;
    float4 bv = reinterpret_cast<const float4*>(bias)[lane];
    float4 o = {acc.x * inv + bv.x, acc.y * inv + bv.y,
                acc.z * inv + bv.z, acc.w * inv + bv.w};
    reinterpret_cast<float4*>(out)[node * 32 + lane] = o;
}

// ---------------------------------------------------------------------------
extern "C" void kernel_launch(void* const* d_in, const int* in_sizes, int n_in,
                              void* d_out, int out_size) {
    const float* x     = (const float*)d_in[0];
    const int*   ei    = (const int*)  d_in[1];
    const float* W     = (const float*)d_in[2];
    const float* bproj = (const float*)d_in[3];
    const float* att_s = (const float*)d_in[4];
    const float* att_d = (const float*)d_in[5];
    const float* bias  = (const float*)d_in[6];
    float* out = (float*)d_out;

    const int n = in_sizes[0] / 128;
    const int E = in_sizes[1] / 2;
    const int nb = (n + 1023) >> 10;

    static cudaStream_t s_csr = nullptr;
    static cudaEvent_t ev_fork = nullptr, ev_join = nullptr;
    if (!s_csr) {
        cudaStreamCreateWithFlags(&s_csr, cudaStreamNonBlocking);
        cudaEventCreateWithFlags(&ev_fork, cudaEventDisableTiming);
        cudaEventCreateWithFlags(&ev_join, cudaEventDisableTiming);
    }

    cudaEventRecord(ev_fork, 0);
    cudaStreamWaitEvent(s_csr, ev_fork, 0);
    zero_kernel<<<(n + 255) / 256, 256, 0, s_csr>>>(n);
    hist_kernel<<<(E + 255) / 256, 256, 0, s_csr>>>(ei, E);
    scan1_kernel<<<nb, 256, 0, s_csr>>>(n);
    scan3_kernel<<<nb, 256, 0, s_csr>>>(n, nb);
    fill_kernel<<<(E + 255) / 256, 256, 0, s_csr>>>(ei, E);
    cudaEventRecord(ev_join, s_csr);

    gemm_kernel<<<(n + 63) / 64, 256>>>(x, W, bproj, att_s, att_d, n);

    cudaStreamWaitEvent(0, ev_join, 0);
    gather_kernel<<<(n + 1) / 2, 64>>>(bias, out, n);
}

// round 8
// speedup vs baseline: 1.1481x; 1.1481x over previous
#include <cuda_runtime.h>
#include <cuda_fp16.h>

// Problem constants: N=100000, E=1600000, DIM=128, HEADS=8, HEAD_DIM=16
#define NMAX 100000
#define EMAX 1600000

static __device__ __half g_xh_h[NMAX * 128];   // projected features, fp16 [N,128]
static __device__ float  g_asrc[NMAX * 8];     // per-node src logits [N,H]
static __device__ float  g_adst[NMAX * 8];     // per-node dst logits [N,H]
static __device__ int    g_cnt[NMAX];          // in-degree
static __device__ int    g_off[NMAX];          // CSR offsets
static __device__ int    g_bsum[128];          // scan block sums
static __device__ int    g_epos[EMAX];         // within-segment position per edge
static __device__ int    g_csrc[EMAX];         // CSR: src per dst-sorted edge

__device__ __forceinline__ float lrelu(float s) { return (s > 0.f) ? s : 0.2f * s; }

#define LDSM4(r0, r1, r2, r3, addr)                                           \
    asm volatile("ldmatrix.sync.aligned.m8n8.x4.shared.b16 {%0,%1,%2,%3}, [%4];" \
                 : "=r"(r0), "=r"(r1), "=r"(r2), "=r"(r3) : "r"(addr))

#define MMA16816(d, a0, a1, a2, a3, b0, b1)                                   \
    asm volatile("mma.sync.aligned.m16n8k16.row.col.f32.f16.f16.f32 "         \
                 "{%0,%1,%2,%3}, {%4,%5,%6,%7}, {%8,%9}, {%0,%1,%2,%3};"      \
                 : "+f"(d[0]), "+f"(d[1]), "+f"(d[2]), "+f"(d[3])             \
                 : "r"(a0), "r"(a1), "r"(a2), "r"(a3), "r"(b0), "r"(b1))

// ---------------------------------------------------------------------------
// Tensor-core GEMM: xh = x @ W^T + b_proj.
// Grid (2, ceil(n/128)): blockIdx.x = column half (64 cols), blockIdx.y = row tile.
// W split into fp16 hi + fp16 residual -> GEMM error limited to x's fp16 rounding.
// Epilogue: fp16 xh store + fused per-(row,head) attention logits.
// SMEM: xs[128][136] fp16 (34816B) + wh[64][136] + wl[64][136] (17408B each).
// ---------------------------------------------------------------------------
__global__ __launch_bounds__(256) void gemm_tc(const float* __restrict__ x,
                                               const float* __restrict__ W,
                                               const float* __restrict__ b,
                                               const float* __restrict__ att_s,
                                               const float* __restrict__ att_d,
                                               int n) {
    extern __shared__ __half sm[];
    __half* xs = sm;                 // [128][136]
    __half* wh = sm + 128 * 136;     // [64][136]
    __half* wl = wh + 64 * 136;      // [64][136]

    const int t = threadIdx.x;
    const int by = blockIdx.x;             // 0/1: columns by*64 .. by*64+63
    const int row0 = blockIdx.y * 128;
    const int cbase = by * 64;

    // ---- load x tile (128 x 128 fp32 -> fp16), coalesced float4 ----
#pragma unroll
    for (int i = 0; i < 16; i++) {
        int idx = t + i * 256;       // 0..4095 float4s
        int r = idx >> 5, kq = idx & 31;
        float4 v = make_float4(0.f, 0.f, 0.f, 0.f);
        if (row0 + r < n)
            v = *reinterpret_cast<const float4*>(&x[(row0 + r) * 128 + kq * 4]);
        union { __half2 h2[2]; uint2 u; } pk;
        pk.h2[0] = __floats2half2_rn(v.x, v.y);
        pk.h2[1] = __floats2half2_rn(v.z, v.w);
        *reinterpret_cast<uint2*>(&xs[r * 136 + kq * 4]) = pk.u;
    }
    // ---- load W rows cbase..cbase+63, split hi/lo ----
#pragma unroll
    for (int i = 0; i < 8; i++) {
        int idx = t + i * 256;       // 0..2047 float4s
        int r = idx >> 5, kq = idx & 31;
        float4 v = *reinterpret_cast<const float4*>(&W[(cbase + r) * 128 + kq * 4]);
        __half hx = __float2half_rn(v.x), hy = __float2half_rn(v.y);
        __half hz = __float2half_rn(v.z), hw = __float2half_rn(v.w);
        union { __half2 h2[2]; uint2 u; } ph, pl;
        ph.h2[0] = __halves2half2(hx, hy);
        ph.h2[1] = __halves2half2(hz, hw);
        pl.h2[0] = __floats2half2_rn(v.x - __half2float(hx), v.y - __half2float(hy));
        pl.h2[1] = __floats2half2_rn(v.z - __half2float(hz), v.w - __half2float(hw));
        *reinterpret_cast<uint2*>(&wh[r * 136 + kq * 4]) = ph.u;
        *reinterpret_cast<uint2*>(&wl[r * 136 + kq * 4]) = pl.u;
    }
    __syncthreads();

    const int lane = t & 31, wid = t >> 5;
    const int wm0 = (wid >> 1) * 32;   // warp rows (32)
    const int wn0 = (wid & 1) * 32;    // warp cols (32, within the 64)

    const unsigned xsA = (unsigned)__cvta_generic_to_shared(xs);
    const unsigned whA = (unsigned)__cvta_generic_to_shared(wh);
    const unsigned wlA = (unsigned)__cvta_generic_to_shared(wl);

    const int arow = lane & 15;
    const int acol = (lane >> 4) * 8;
    const int bnof = (lane & 7) + ((lane >> 1) & 8);   // n offset within 16-group
    const int bkof = ((lane >> 3) & 1) * 8;            // k offset 0/8

    float acc[2][4][4];
#pragma unroll
    for (int mt = 0; mt < 2; mt++)
#pragma unroll
        for (int nt = 0; nt < 4; nt++)
#pragma unroll
            for (int r = 0; r < 4; r++) acc[mt][nt][r] = 0.f;

#pragma unroll
    for (int kk = 0; kk < 8; kk++) {
        const int k0 = kk * 16;
        unsigned a[2][4];
#pragma unroll
        for (int mt = 0; mt < 2; mt++) {
            unsigned addr = xsA + ((wm0 + mt * 16 + arow) * 136 + k0 + acol) * 2;
            LDSM4(a[mt][0], a[mt][1], a[mt][2], a[mt][3], addr);
        }
        unsigned bh[2][4], bl[2][4];
#pragma unroll
        for (int ng = 0; ng < 2; ng++) {
            unsigned off = ((wn0 + ng * 16 + bnof) * 136 + k0 + bkof) * 2;
            LDSM4(bh[ng][0], bh[ng][1], bh[ng][2], bh[ng][3], whA + off);
            LDSM4(bl[ng][0], bl[ng][1], bl[ng][2], bl[ng][3], wlA + off);
        }
#pragma unroll
        for (int mt = 0; mt < 2; mt++)
#pragma unroll
            for (int ng = 0; ng < 2; ng++)
#pragma unroll
                for (int sub = 0; sub < 2; sub++) {
                    MMA16816(acc[mt][ng * 2 + sub], a[mt][0], a[mt][1], a[mt][2], a[mt][3],
                             bh[ng][sub * 2], bh[ng][sub * 2 + 1]);
                    MMA16816(acc[mt][ng * 2 + sub], a[mt][0], a[mt][1], a[mt][2], a[mt][3],
                             bl[ng][sub * 2], bl[ng][sub * 2 + 1]);
                }
    }

    // ---- stage result tile (fp32 -> fp16, + bias) in SMEM, pitch 72 ----
    __syncthreads();                 // done reading xs; reuse as S
    __half* S = xs;                  // [128][72]
#pragma unroll
    for (int mt = 0; mt < 2; mt++)
#pragma unroll
        for (int nt = 0; nt < 4; nt++) {
            int r = wm0 + mt * 16 + (lane >> 2);
            int c = wn0 + nt * 8 + (lane & 3) * 2;
            float bc0 = __ldg(&b[cbase + c]), bc1 = __ldg(&b[cbase + c + 1]);
            *reinterpret_cast<__half2*>(&S[r * 72 + c]) =
                __floats2half2_rn(acc[mt][nt][0] + bc0, acc[mt][nt][1] + bc1);
            *reinterpret_cast<__half2*>(&S[(r + 8) * 72 + c]) =
                __floats2half2_rn(acc[mt][nt][2] + bc0, acc[mt][nt][3] + bc1);
        }
    __syncthreads();

    // ---- output pass: write xh + compute 2 full head logits per thread ----
    {
        int row = t >> 1, hh = t & 1;
        int grow = row0 + row;
        if (grow < n) {
            int c0 = hh * 32;                       // local col base
            int hb = by * 4 + hh * 2;               // global head base (2 heads)
            float sd[2] = {0.f, 0.f}, dd[2] = {0.f, 0.f};
#pragma unroll
            for (int q = 0; q < 4; q++) {
                uint4 u = *reinterpret_cast<uint4*>(&S[row * 72 + c0 + q * 8]);
                *reinterpret_cast<uint4*>(&g_xh_h[grow * 128 + cbase + c0 + q * 8]) = u;
                int hs = q >> 1;                    // head select within pair
                const unsigned* uw = reinterpret_cast<const unsigned*>(&u);
#pragma unroll
                for (int p = 0; p < 4; p++) {
                    float2 f = __half22float2(*reinterpret_cast<const __half2*>(&uw[p]));
                    int gc = cbase + c0 + q * 8 + p * 2;
                    sd[hs] += f.x * __ldg(&att_s[gc]) + f.y * __ldg(&att_s[gc + 1]);
                    dd[hs] += f.x * __ldg(&att_d[gc]) + f.y * __ldg(&att_d[gc + 1]);
                }
            }
            *reinterpret_cast<float2*>(&g_asrc[grow * 8 + hb]) = make_float2(sd[0], sd[1]);
            *reinterpret_cast<float2*>(&g_adst[grow * 8 + hb]) = make_float2(dd[0], dd[1]);
        }
    }
}

// ---------------------------------------------------------------------------
// CSR construction
// ---------------------------------------------------------------------------
__global__ __launch_bounds__(256) void zero_kernel(int n) {
    int t = blockIdx.x * 256 + threadIdx.x;
    if (t < n) g_cnt[t] = 0;
}

__global__ __launch_bounds__(256) void hist_kernel(const int* __restrict__ ei, int E) {
    int e = blockIdx.x * 256 + threadIdx.x;
    if (e < E) g_epos[e] = atomicAdd(&g_cnt[ei[E + e]], 1);
}

__global__ __launch_bounds__(256) void scan1_kernel(int n) {
    __shared__ int s[256];
    int b = blockIdx.x, t = threadIdx.x;
    int base = b * 1024 + t * 4;
    int v[4];
#pragma unroll
    for (int j = 0; j < 4; j++) v[j] = (base + j < n) ? g_cnt[base + j] : 0;
    int local = v[0] + v[1] + v[2] + v[3];
    s[t] = local;
    __syncthreads();
    for (int off = 1; off < 256; off <<= 1) {
        int xv = (t >= off) ? s[t - off] : 0;
        __syncthreads();
        s[t] += xv;
        __syncthreads();
    }
    int run = s[t] - local;
#pragma unroll
    for (int j = 0; j < 4; j++) {
        if (base + j < n) g_off[base + j] = run;
        run += v[j];
    }
    if (t == 255) g_bsum[b] = s[255];
}

__global__ __launch_bounds__(256) void scan3_kernel(int n, int nb) {
    __shared__ int s[128];
    int b = blockIdx.x, t = threadIdx.x;
    if (t < 128) s[t] = (t < b) ? g_bsum[t] : 0;
    __syncthreads();
    if (t < 64) s[t] += s[t + 64];
    __syncthreads();
    if (t < 32) {
        int v = s[t] + s[t + 32];
        v += __shfl_down_sync(0xffffffffu, v, 16);
        v += __shfl_down_sync(0xffffffffu, v, 8);
        v += __shfl_down_sync(0xffffffffu, v, 4);
        v += __shfl_down_sync(0xffffffffu, v, 2);
        v += __shfl_down_sync(0xffffffffu, v, 1);
        if (t == 0) s[0] = v;
    }
    __syncthreads();
    int add = s[0];
    int base = b * 1024 + t * 4;
#pragma unroll
    for (int j = 0; j < 4; j++)
        if (base + j < n) g_off[base + j] += add;
}

__global__ __launch_bounds__(256) void fill_kernel(const int* __restrict__ ei, int E) {
    int e = blockIdx.x * 256 + threadIdx.x;
    if (e >= E) return;
    g_csrc[g_off[ei[E + e]] + g_epos[e]] = ei[e];
}

// ---------------------------------------------------------------------------
// Fused gather (best-measured R5 variant): 2 warps/CTA, one node per warp.
// Per-lane csrc prefetch + shfl distribution; direct per-edge logit loads.
// NOTE: bias already folded into xh by the GEMM epilogue.
// ---------------------------------------------------------------------------
__global__ __launch_bounds__(64) void gather_kernel(float* __restrict__ out, int n) {
    int node = blockIdx.x * 2 + (threadIdx.x >> 5);
    int lane = threadIdx.x & 31;
    if (node >= n) return;
    const uint2* xh2 = reinterpret_cast<const uint2*>(g_xh_h);
    const int hoff = lane >> 2;

    float ad = __ldg(&g_adst[node * 8 + hoff]);
    float s0 = __ldg(&g_asrc[node * 8 + hoff]) + ad;
    float ex = __expf(lrelu(s0));
    float dsum = ex;

    uint2 sv = __ldg(&xh2[node * 32 + lane]);
    float2 f0 = __half22float2(*reinterpret_cast<__half2*>(&sv.x));
    float2 f1 = __half22float2(*reinterpret_cast<__half2*>(&sv.y));
    float4 acc = {ex * f0.x, ex * f0.y, ex * f1.x, ex * f1.y};

    const int beg = __ldg(&g_off[node]), cnt = __ldg(&g_cnt[node]);

    for (int c0 = 0; c0 < cnt; c0 += 32) {
        const int rem = min(cnt - c0, 32);
        int myidx = (lane < rem) ? __ldg(&g_csrc[beg + c0 + lane]) : 0;

        int j = 0;
        for (; j + 4 <= rem; j += 4) {
            int sA = __shfl_sync(0xffffffffu, myidx, j);
            int sB = __shfl_sync(0xffffffffu, myidx, j + 1);
            int sC = __shfl_sync(0xffffffffu, myidx, j + 2);
            int sD = __shfl_sync(0xffffffffu, myidx, j + 3);
            float aA = __ldg(&g_asrc[sA * 8 + hoff]);
            float aB = __ldg(&g_asrc[sB * 8 + hoff]);
            float aC = __ldg(&g_asrc[sC * 8 + hoff]);
            float aD = __ldg(&g_asrc[sD * 8 + hoff]);
            uint2 vA = __ldg(&xh2[sA * 32 + lane]);
            uint2 vB = __ldg(&xh2[sB * 32 + lane]);
            uint2 vC = __ldg(&xh2[sC * 32 + lane]);
            uint2 vD = __ldg(&xh2[sD * 32 + lane]);
            float eA = __expf(lrelu(aA + ad));
            float eB = __expf(lrelu(aB + ad));
            float eC = __expf(lrelu(aC + ad));
            float eD = __expf(lrelu(aD + ad));
            dsum += eA + eB + eC + eD;
            float2 a0 = __half22float2(*reinterpret_cast<__half2*>(&vA.x));
            float2 a1 = __half22float2(*reinterpret_cast<__half2*>(&vA.y));
            float2 b0 = __half22float2(*reinterpret_cast<__half2*>(&vB.x));
            float2 b1 = __half22float2(*reinterpret_cast<__half2*>(&vB.y));
            float2 c4 = __half22float2(*reinterpret_cast<__half2*>(&vC.x));
            float2 c1 = __half22float2(*reinterpret_cast<__half2*>(&vC.y));
            float2 d0 = __half22float2(*reinterpret_cast<__half2*>(&vD.x));
            float2 d1 = __half22float2(*reinterpret_cast<__half2*>(&vD.y));
            acc.x += eA * a0.x + eB * b0.x + eC * c4.x + eD * d0.x;
            acc.y += eA * a0.y + eB * b0.y + eC * c4.y + eD * d0.y;
            acc.z += eA * a1.x + eB * b1.x + eC * c1.x + eD * d1.x;
            acc.w += eA * a1.y + eB * b1.y + eC * c1.y + eD * d1.y;
        }
        for (; j < rem; j++) {
            int s = __shfl_sync(0xffffffffu, myidx, j);
            float a = __ldg(&g_asrc[s * 8 + hoff]) + ad;
            float e = __expf(lrelu(a));
            dsum += e;
            uint2 v = __ldg(&xh2[s * 32 + lane]);
            float2 p0 = __half22float2(*reinterpret_cast<__half2*>(&v.x));
            float2 p1 = __half22float2(*reinterpret_cast<__half2*>(&v.y));
            acc.x += e * p0.x; acc.y += e * p0.y; acc.z += e * p1.x; acc.w += e * p1.y;
        }
    }

    float inv = 1.0f / dsum;
    float4 o = {acc.x * inv, acc.y * inv, acc.z * inv, acc.w * inv};
    reinterpret_cast<float4*>(out)[node * 32 + lane] = o;
}

// ---------------------------------------------------------------------------
extern "C" void kernel_launch(void* const* d_in, const int* in_sizes, int n_in,
                              void* d_out, int out_size) {
    const float* x     = (const float*)d_in[0];
    const int*   ei    = (const int*)  d_in[1];
    const float* W     = (const float*)d_in[2];
    const float* bproj = (const float*)d_in[3];
    const float* att_s = (const float*)d_in[4];
    const float* att_d = (const float*)d_in[5];
    const float* bias  = (const float*)d_in[6];
    float* out = (float*)d_out;

    const int n = in_sizes[0] / 128;
    const int E = in_sizes[1] / 2;
    const int nb = (n + 1023) >> 10;
    const int smem_bytes = (128 * 136 + 2 * 64 * 136) * 2;   // 69632

    static cudaStream_t s_csr = nullptr;
    static cudaEvent_t ev_fork = nullptr, ev_join = nullptr;
    if (!s_csr) {
        cudaStreamCreateWithFlags(&s_csr, cudaStreamNonBlocking);
        cudaEventCreateWithFlags(&ev_fork, cudaEventDisableTiming);
        cudaEventCreateWithFlags(&ev_join, cudaEventDisableTiming);
        cudaFuncSetAttribute(gemm_tc, cudaFuncAttributeMaxDynamicSharedMemorySize,
                             smem_bytes);
    }

    // NOTE: bias (the final output bias) equals b_proj-style additive term that
    // the reference adds at the end; since softmax weights sum to 1 we fold it
    // into xh via the GEMM epilogue ONLY if it distributes — it does NOT for
    // b_proj vs bias separately. The GEMM epilogue adds b_proj (part of xh by
    // definition). The final `bias` is added via the gather epilogue... but we
    // folded it into xh instead: out = sum(w * (xh)) + bias. Since sum(w)=1,
    // sum(w*(xh + bias)) = sum(w*xh) + bias. So fold `bias` into the S tile too
    // — done by passing (b_proj + bias) to the GEMM? They have the same shape.
    // b_proj affects logits; bias must NOT. So we keep them separate: b_proj is
    // added before logits (in S), and `bias` is added in gather... BUT gather
    // no longer adds bias. To keep logits correct AND exploit sum(w)=1, we add
    // `bias` into xh AFTER logit computation is impossible (xh shared). Instead
    // gather output adds bias implicitly by folding into xh would corrupt
    // logits. Resolution: bias is all-zeros in this dataset? Not guaranteed.
    // Safe route: add bias in gather epilogue via a tiny second pass below.
    gemm_tc<<<dim3(2, (n + 127) / 128), 256, smem_bytes>>>(x, W, bproj, att_s, att_d, n);

    cudaEventRecord(ev_fork, 0);
    cudaStreamWaitEvent(s_csr, ev_fork, 0);
    // (CSR chain actually independent of gemm; fork before gemm would be
    // better, but events are recorded relative to launch order on stream 0.)
    cudaEventRecord(ev_join, s_csr);

    // Re-issue CSR chain on the side stream concurrent with gemm: record fork
    // BEFORE gemm for true overlap.
    (void)ev_join;

    // --- proper ordering (fork before gemm) ---
    // The sequence above placed gemm first on stream 0; the CSR chain below is
    // allowed to run concurrently because it only waits on ev_fork2.
    static cudaEvent_t ev_fork2 = nullptr, ev_join2 = nullptr;
    if (!ev_fork2) {
        cudaEventCreateWithFlags(&ev_fork2, cudaEventDisableTiming);
        cudaEventCreateWithFlags(&ev_join2, cudaEventDisableTiming);
    }
    cudaEventRecord(ev_fork2, 0);   // after gemm enqueue; CSR still overlaps gather-wait
    cudaStreamWaitEvent(s_csr, ev_fork2, 0);
    zero_kernel<<<(n + 255) / 256, 256, 0, s_csr>>>(n);
    hist_kernel<<<(E + 255) / 256, 256, 0, s_csr>>>(ei, E);
    scan1_kernel<<<nb, 256, 0, s_csr>>>(n);
    scan3_kernel<<<nb, 256, 0, s_csr>>>(n, nb);
    fill_kernel<<<(E + 255) / 256, 256, 0, s_csr>>>(ei, E);
    cudaEventRecord(ev_join2, s_csr);

    cudaStreamWaitEvent(0, ev_join2, 0);
    gather_kernel<<<(n + 1) / 2, 64>>>(out, n);

    // add the final bias (bias is NOT folded into xh; logits must exclude it)
    // tiny elementwise pass: out += bias  (100k x 128 = 51MB stream, ~8us)
    // fused here as a lambda-style kernel:
    extern __global__ void bias_add_kernel(const float*, float*, int);
    bias_add_kernel<<<(n * 32 + 255) / 256, 256>>>(bias, out, n);
}

// out[node*128 + c] += bias[c], vectorized float4
__global__ __launch_bounds__(256) void bias_add_kernel(const float* __restrict__ bias,
                                                       float* __restrict__ out, int n) {
    int t = blockIdx.x * 256 + threadIdx.x;
    if (t >= n * 32) return;
    int q = t & 31;
    float4 o = reinterpret_cast<float4*>(out)[t];
    float4 bv = reinterpret_cast<const float4*>(bias)[q];
    o.x += bv.x; o.y += bv.y; o.z += bv.z; o.w += bv.w;
    reinterpret_cast<float4*>(out)[t] = o;
}

// round 9
// speedup vs baseline: 1.2338x; 1.0747x over previous
#include <cuda_runtime.h>
#include <cuda_fp16.h>

// Problem constants: N=100000, E=1600000, DIM=128, HEADS=8, HEAD_DIM=16
#define NMAX 100000
#define EMAX 1600000

static __device__ __half g_xh_h[NMAX * 128];   // projected features, fp16 [N,128]
static __device__ float  g_asrc[NMAX * 8];     // per-node src logits [N,H]
static __device__ float  g_adst[NMAX * 8];     // per-node dst logits [N,H]
static __device__ int    g_cnt[NMAX];          // in-degree
static __device__ int    g_off[NMAX];          // CSR offsets
static __device__ int    g_bsum[128];          // scan block sums
static __device__ int    g_epos[EMAX];         // within-segment position per edge
static __device__ int    g_csrc[EMAX];         // CSR: src per dst-sorted edge

__device__ __forceinline__ float lrelu(float s) { return (s > 0.f) ? s : 0.2f * s; }

#define LDSM4(r0, r1, r2, r3, addr)                                           \
    asm volatile("ldmatrix.sync.aligned.m8n8.x4.shared.b16 {%0,%1,%2,%3}, [%4];" \
                 : "=r"(r0), "=r"(r1), "=r"(r2), "=r"(r3) : "r"(addr))

#define MMA16816(d, a0, a1, a2, a3, b0, b1)                                   \
    asm volatile("mma.sync.aligned.m16n8k16.row.col.f32.f16.f16.f32 "         \
                 "{%0,%1,%2,%3}, {%4,%5,%6,%7}, {%8,%9}, {%0,%1,%2,%3};"      \
                 : "+f"(d[0]), "+f"(d[1]), "+f"(d[2]), "+f"(d[3])             \
                 : "r"(a0), "r"(a1), "r"(a2), "r"(a3), "r"(b0), "r"(b1))

// ---------------------------------------------------------------------------
// Tensor-core GEMM: xh = x @ W^T + b_proj.
// Grid (2, ceil(n/128)): blockIdx.x = column half (64 cols), blockIdx.y = rows.
// W split into fp16 hi + fp16 residual -> GEMM error limited to x's fp16 round.
// Epilogue: fp16 xh store + fused per-(row,head) attention logits.
// ---------------------------------------------------------------------------
__global__ __launch_bounds__(256) void gemm_tc(const float* __restrict__ x,
                                               const float* __restrict__ W,
                                               const float* __restrict__ b,
                                               const float* __restrict__ att_s,
                                               const float* __restrict__ att_d,
                                               int n) {
    extern __shared__ __half sm[];
    __half* xs = sm;                 // [128][136]
    __half* wh = sm + 128 * 136;     // [64][136]
    __half* wl = wh + 64 * 136;      // [64][136]

    const int t = threadIdx.x;
    const int by = blockIdx.x;             // 0/1: columns by*64 .. by*64+63
    const int row0 = blockIdx.y * 128;
    const int cbase = by * 64;

    // ---- load x tile (128 x 128 fp32 -> fp16), coalesced float4 ----
#pragma unroll
    for (int i = 0; i < 16; i++) {
        int idx = t + i * 256;
        int r = idx >> 5, kq = idx & 31;
        float4 v = make_float4(0.f, 0.f, 0.f, 0.f);
        if (row0 + r < n)
            v = *reinterpret_cast<const float4*>(&x[(row0 + r) * 128 + kq * 4]);
        union { __half2 h2[2]; uint2 u; } pk;
        pk.h2[0] = __floats2half2_rn(v.x, v.y);
        pk.h2[1] = __floats2half2_rn(v.z, v.w);
        *reinterpret_cast<uint2*>(&xs[r * 136 + kq * 4]) = pk.u;
    }
    // ---- load W rows cbase..cbase+63, split hi/lo ----
#pragma unroll
    for (int i = 0; i < 8; i++) {
        int idx = t + i * 256;
        int r = idx >> 5, kq = idx & 31;
        float4 v = *reinterpret_cast<const float4*>(&W[(cbase + r) * 128 + kq * 4]);
        __half hx = __float2half_rn(v.x), hy = __float2half_rn(v.y);
        __half hz = __float2half_rn(v.z), hw = __float2half_rn(v.w);
        union { __half2 h2[2]; uint2 u; } ph, pl;
        ph.h2[0] = __halves2half2(hx, hy);
        ph.h2[1] = __halves2half2(hz, hw);
        pl.h2[0] = __floats2half2_rn(v.x - __half2float(hx), v.y - __half2float(hy));
        pl.h2[1] = __floats2half2_rn(v.z - __half2float(hz), v.w - __half2float(hw));
        *reinterpret_cast<uint2*>(&wh[r * 136 + kq * 4]) = ph.u;
        *reinterpret_cast<uint2*>(&wl[r * 136 + kq * 4]) = pl.u;
    }
    __syncthreads();

    const int lane = t & 31, wid = t >> 5;
    const int wm0 = (wid >> 1) * 32;   // warp rows (32)
    const int wn0 = (wid & 1) * 32;    // warp cols (32, within the 64)

    const unsigned xsA = (unsigned)__cvta_generic_to_shared(xs);
    const unsigned whA = (unsigned)__cvta_generic_to_shared(wh);
    const unsigned wlA = (unsigned)__cvta_generic_to_shared(wl);

    const int arow = lane & 15;
    const int acol = (lane >> 4) * 8;
    const int bnof = (lane & 7) + ((lane >> 1) & 8);
    const int bkof = ((lane >> 3) & 1) * 8;

    float acc[2][4][4];
#pragma unroll
    for (int mt = 0; mt < 2; mt++)
#pragma unroll
        for (int nt = 0; nt < 4; nt++)
#pragma unroll
            for (int r = 0; r < 4; r++) acc[mt][nt][r] = 0.f;

#pragma unroll
    for (int kk = 0; kk < 8; kk++) {
        const int k0 = kk * 16;
        unsigned a[2][4];
#pragma unroll
        for (int mt = 0; mt < 2; mt++) {
            unsigned addr = xsA + ((wm0 + mt * 16 + arow) * 136 + k0 + acol) * 2;
            LDSM4(a[mt][0], a[mt][1], a[mt][2], a[mt][3], addr);
        }
        unsigned bh[2][4], bl[2][4];
#pragma unroll
        for (int ng = 0; ng < 2; ng++) {
            unsigned off = ((wn0 + ng * 16 + bnof) * 136 + k0 + bkof) * 2;
            LDSM4(bh[ng][0], bh[ng][1], bh[ng][2], bh[ng][3], whA + off);
            LDSM4(bl[ng][0], bl[ng][1], bl[ng][2], bl[ng][3], wlA + off);
        }
#pragma unroll
        for (int mt = 0; mt < 2; mt++)
#pragma unroll
            for (int ng = 0; ng < 2; ng++)
#pragma unroll
                for (int sub = 0; sub < 2; sub++) {
                    MMA16816(acc[mt][ng * 2 + sub], a[mt][0], a[mt][1], a[mt][2], a[mt][3],
                             bh[ng][sub * 2], bh[ng][sub * 2 + 1]);
                    MMA16816(acc[mt][ng * 2 + sub], a[mt][0], a[mt][1], a[mt][2], a[mt][3],
                             bl[ng][sub * 2], bl[ng][sub * 2 + 1]);
                }
    }

    // ---- stage result tile (fp32 -> fp16, + b_proj) in SMEM, pitch 72 ----
    __syncthreads();
    __half* S = xs;                  // [128][72]
#pragma unroll
    for (int mt = 0; mt < 2; mt++)
#pragma unroll
        for (int nt = 0; nt < 4; nt++) {
            int r = wm0 + mt * 16 + (lane >> 2);
            int c = wn0 + nt * 8 + (lane & 3) * 2;
            float bc0 = __ldg(&b[cbase + c]), bc1 = __ldg(&b[cbase + c + 1]);
            *reinterpret_cast<__half2*>(&S[r * 72 + c]) =
                __floats2half2_rn(acc[mt][nt][0] + bc0, acc[mt][nt][1] + bc1);
            *reinterpret_cast<__half2*>(&S[(r + 8) * 72 + c]) =
                __floats2half2_rn(acc[mt][nt][2] + bc0, acc[mt][nt][3] + bc1);
        }
    __syncthreads();

    // ---- output pass: write xh + compute 2 full head logits per thread ----
    {
        int row = t >> 1, hh = t & 1;
        int grow = row0 + row;
        if (grow < n) {
            int c0 = hh * 32;
            int hb = by * 4 + hh * 2;
            float sd[2] = {0.f, 0.f}, dd[2] = {0.f, 0.f};
#pragma unroll
            for (int q = 0; q < 4; q++) {
                uint4 u = *reinterpret_cast<uint4*>(&S[row * 72 + c0 + q * 8]);
                *reinterpret_cast<uint4*>(&g_xh_h[grow * 128 + cbase + c0 + q * 8]) = u;
                int hs = q >> 1;
                const unsigned* uw = reinterpret_cast<const unsigned*>(&u);
#pragma unroll
                for (int p = 0; p < 4; p++) {
                    float2 f = __half22float2(*reinterpret_cast<const __half2*>(&uw[p]));
                    int gc = cbase + c0 + q * 8 + p * 2;
                    sd[hs] += f.x * __ldg(&att_s[gc]) + f.y * __ldg(&att_s[gc + 1]);
                    dd[hs] += f.x * __ldg(&att_d[gc]) + f.y * __ldg(&att_d[gc + 1]);
                }
            }
            *reinterpret_cast<float2*>(&g_asrc[grow * 8 + hb]) = make_float2(sd[0], sd[1]);
            *reinterpret_cast<float2*>(&g_adst[grow * 8 + hb]) = make_float2(dd[0], dd[1]);
        }
    }
}

// ---------------------------------------------------------------------------
// CSR construction
// ---------------------------------------------------------------------------
__global__ __launch_bounds__(256) void zero_kernel(int n) {
    int t = blockIdx.x * 256 + threadIdx.x;
    if (t < n) g_cnt[t] = 0;
}

__global__ __launch_bounds__(256) void hist_kernel(const int* __restrict__ ei, int E) {
    int e = blockIdx.x * 256 + threadIdx.x;
    if (e < E) g_epos[e] = atomicAdd(&g_cnt[ei[E + e]], 1);
}

__global__ __launch_bounds__(256) void scan1_kernel(int n) {
    __shared__ int s[256];
    int b = blockIdx.x, t = threadIdx.x;
    int base = b * 1024 + t * 4;
    int v[4];
#pragma unroll
    for (int j = 0; j < 4; j++) v[j] = (base + j < n) ? g_cnt[base + j] : 0;
    int local = v[0] + v[1] + v[2] + v[3];
    s[t] = local;
    __syncthreads();
    for (int off = 1; off < 256; off <<= 1) {
        int xv = (t >= off) ? s[t - off] : 0;
        __syncthreads();
        s[t] += xv;
        __syncthreads();
    }
    int run = s[t] - local;
#pragma unroll
    for (int j = 0; j < 4; j++) {
        if (base + j < n) g_off[base + j] = run;
        run += v[j];
    }
    if (t == 255) g_bsum[b] = s[255];
}

__global__ __launch_bounds__(256) void scan3_kernel(int n, int nb) {
    __shared__ int s[128];
    int b = blockIdx.x, t = threadIdx.x;
    if (t < 128) s[t] = (t < b) ? g_bsum[t] : 0;
    __syncthreads();
    if (t < 64) s[t] += s[t + 64];
    __syncthreads();
    if (t < 32) {
        int v = s[t] + s[t + 32];
        v += __shfl_down_sync(0xffffffffu, v, 16);
        v += __shfl_down_sync(0xffffffffu, v, 8);
        v += __shfl_down_sync(0xffffffffu, v, 4);
        v += __shfl_down_sync(0xffffffffu, v, 2);
        v += __shfl_down_sync(0xffffffffu, v, 1);
        if (t == 0) s[0] = v;
    }
    __syncthreads();
    int add = s[0];
    int base = b * 1024 + t * 4;
#pragma unroll
    for (int j = 0; j < 4; j++)
        if (base + j < n) g_off[base + j] += add;
}

__global__ __launch_bounds__(256) void fill_kernel(const int* __restrict__ ei, int E) {
    int e = blockIdx.x * 256 + threadIdx.x;
    if (e >= E) return;
    g_csrc[g_off[ei[E + e]] + g_epos[e]] = ei[e];
}

// ---------------------------------------------------------------------------
// Fused gather: 2 warps/CTA, one node per warp; per-lane csrc prefetch + shfl
// distribution; direct per-edge logit loads; final bias added in epilogue.
// ---------------------------------------------------------------------------
__global__ __launch_bounds__(64) void gather_kernel(const float* __restrict__ bias,
                                                    float* __restrict__ out, int n) {
    int node = blockIdx.x * 2 + (threadIdx.x >> 5);
    int lane = threadIdx.x & 31;
    if (node >= n) return;
    const uint2* xh2 = reinterpret_cast<const uint2*>(g_xh_h);
    const int hoff = lane >> 2;

    float ad = __ldg(&g_adst[node * 8 + hoff]);
    float s0 = __ldg(&g_asrc[node * 8 + hoff]) + ad;
    float ex = __expf(lrelu(s0));
    float dsum = ex;

    uint2 sv = __ldg(&xh2[node * 32 + lane]);
    float2 f0 = __half22float2(*reinterpret_cast<__half2*>(&sv.x));
    float2 f1 = __half22float2(*reinterpret_cast<__half2*>(&sv.y));
    float4 acc = {ex * f0.x, ex * f0.y, ex * f1.x, ex * f1.y};

    const int beg = __ldg(&g_off[node]), cnt = __ldg(&g_cnt[node]);

    for (int c0 = 0; c0 < cnt; c0 += 32) {
        const int rem = min(cnt - c0, 32);
        int myidx = (lane < rem) ? __ldg(&g_csrc[beg + c0 + lane]) : 0;

        int j = 0;
        for (; j + 4 <= rem; j += 4) {
            int sA = __shfl_sync(0xffffffffu, myidx, j);
            int sB = __shfl_sync(0xffffffffu, myidx, j + 1);
            int sC = __shfl_sync(0xffffffffu, myidx, j + 2);
            int sD = __shfl_sync(0xffffffffu, myidx, j + 3);
            float aA = __ldg(&g_asrc[sA * 8 + hoff]);
            float aB = __ldg(&g_asrc[sB * 8 + hoff]);
            float aC = __ldg(&g_asrc[sC * 8 + hoff]);
            float aD = __ldg(&g_asrc[sD * 8 + hoff]);
            uint2 vA = __ldg(&xh2[sA * 32 + lane]);
            uint2 vB = __ldg(&xh2[sB * 32 + lane]);
            uint2 vC = __ldg(&xh2[sC * 32 + lane]);
            uint2 vD = __ldg(&xh2[sD * 32 + lane]);
            float eA = __expf(lrelu(aA + ad));
            float eB = __expf(lrelu(aB + ad));
            float eC = __expf(lrelu(aC + ad));
            float eD = __expf(lrelu(aD + ad));
            dsum += eA + eB + eC + eD;
            float2 a0 = __half22float2(*reinterpret_cast<__half2*>(&vA.x));
            float2 a1 = __half22float2(*reinterpret_cast<__half2*>(&vA.y));
            float2 b0 = __half22float2(*reinterpret_cast<__half2*>(&vB.x));
            float2 b1 = __half22float2(*reinterpret_cast<__half2*>(&vB.y));
            float2 c4 = __half22float2(*reinterpret_cast<__half2*>(&vC.x));
            float2 c1 = __half22float2(*reinterpret_cast<__half2*>(&vC.y));
            float2 d0 = __half22float2(*reinterpret_cast<__half2*>(&vD.x));
            float2 d1 = __half22float2(*reinterpret_cast<__half2*>(&vD.y));
            acc.x += eA * a0.x + eB * b0.x + eC * c4.x + eD * d0.x;
            acc.y += eA * a0.y + eB * b0.y + eC * c4.y + eD * d0.y;
            acc.z += eA * a1.x + eB * b1.x + eC * c1.x + eD * d1.x;
            acc.w += eA * a1.y + eB * b1.y + eC * c1.y + eD * d1.y;
        }
        for (; j < rem; j++) {
            int s = __shfl_sync(0xffffffffu, myidx, j);
            float a = __ldg(&g_asrc[s * 8 + hoff]) + ad;
            float e = __expf(lrelu(a));
            dsum += e;
            uint2 v = __ldg(&xh2[s * 32 + lane]);
            float2 p0 = __half22float2(*reinterpret_cast<__half2*>(&v.x));
            float2 p1 = __half22float2(*reinterpret_cast<__half2*>(&v.y));
            acc.x += e * p0.x; acc.y += e * p0.y; acc.z += e * p1.x; acc.w += e * p1.y;
        }
    }

    float inv = 1.0f / dsum;
    float4 bv = __ldg(&reinterpret_cast<const float4*>(bias)[lane]);
    float4 o = {acc.x * inv + bv.x, acc.y * inv + bv.y,
                acc.z * inv + bv.z, acc.w * inv + bv.w};
    reinterpret_cast<float4*>(out)[node * 32 + lane] = o;
}

// ---------------------------------------------------------------------------
extern "C" void kernel_launch(void* const* d_in, const int* in_sizes, int n_in,
                              void* d_out, int out_size) {
    const float* x     = (const float*)d_in[0];
    const int*   ei    = (const int*)  d_in[1];
    const float* W     = (const float*)d_in[2];
    const float* bproj = (const float*)d_in[3];
    const float* att_s = (const float*)d_in[4];
    const float* att_d = (const float*)d_in[5];
    const float* bias  = (const float*)d_in[6];
    float* out = (float*)d_out;

    const int n = in_sizes[0] / 128;
    const int E = in_sizes[1] / 2;
    const int nb = (n + 1023) >> 10;
    const int smem_bytes = (128 * 136 + 2 * 64 * 136) * 2;   // 69632

    static cudaStream_t s_csr = nullptr;
    static cudaEvent_t ev_fork = nullptr, ev_join = nullptr;
    if (!s_csr) {
        cudaStreamCreateWithFlags(&s_csr, cudaStreamNonBlocking);
        cudaEventCreateWithFlags(&ev_fork, cudaEventDisableTiming);
        cudaEventCreateWithFlags(&ev_join, cudaEventDisableTiming);
        cudaFuncSetAttribute(gemm_tc, cudaFuncAttributeMaxDynamicSharedMemorySize,
                             smem_bytes);
    }

    // Fork BEFORE the GEMM so the CSR chain truly overlaps it.
    cudaEventRecord(ev_fork, 0);
    cudaStreamWaitEvent(s_csr, ev_fork, 0);
    zero_kernel<<<(n + 255) / 256, 256, 0, s_csr>>>(n);
    hist_kernel<<<(E + 255) / 256, 256, 0, s_csr>>>(ei, E);
    scan1_kernel<<<nb, 256, 0, s_csr>>>(n);
    scan3_kernel<<<nb, 256, 0, s_csr>>>(n, nb);
    fill_kernel<<<(E + 255) / 256, 256, 0, s_csr>>>(ei, E);
    cudaEventRecord(ev_join, s_csr);

    gemm_tc<<<dim3(2, (n + 127) / 128), 256, smem_bytes>>>(x, W, bproj, att_s, att_d, n);

    cudaStreamWaitEvent(0, ev_join, 0);
    gather_kernel<<<(n + 1) / 2, 64>>>(bias, out, n);
}